// round 15
// baseline (speedup 1.0000x reference)
#include <cuda_runtime.h>
#include <cuda_fp16.h>
#include <cstdint>
#include <math.h>

#define BB 4
#define TT 2048
#define CC 1024
#define MTOT (BB*TT)
#define SCALE 0.03125f

#define NTH 256
#define STAGE_B 32768      // A 16KB (128x64) + B 16KB (128x64) per stage
#define STAGES 3
#define DYN_B (STAGES*STAGE_B + 128)
#define NPERS 296          // persistent CTAs (148 SMs x 2)

#define NT_QKV 1536        // 24 n-tiles x 64 m-tiles
#define NT_SCO 544         // 4 x 136 triangular
#define NT_PV  512         // 4 x 16 x 8

// ------------------------- device scratch (no allocs) -----------------------
__device__ __half g_xh[MTOT*CC];
__device__ __half g_wt[3*CC*CC];                    // W^T fp16 [sel*1024+n][k]
__device__ __half g_qh[MTOT*CC];                    // q * SCALE
__device__ __half g_kh[MTOT*CC];
__device__ __half g_vt[(size_t)BB*CC*TT];           // V^T per batch [c][token]
__device__ float  g_s[(size_t)BB*TT*TT];
__device__ __half g_ph[(size_t)BB*TT*TT];
__device__ unsigned int g_ctr_qkv, g_ctr_sco, g_ctr_pv;

// ------------------------- ptx helpers --------------------------------------
__device__ __forceinline__ uint32_t smem_u32(const void* p) {
    uint32_t a;
    asm("{ .reg .u64 t; cvta.to.shared.u64 t, %1; cvt.u32.u64 %0, t; }" : "=r"(a) : "l"(p));
    return a;
}
#define CP_ASYNC16(dst, src) \
    asm volatile("cp.async.cg.shared.global [%0], [%1], 16;" :: "r"(dst), "l"(src))
#define CP_COMMIT() asm volatile("cp.async.commit_group;" ::: "memory")
#define CP_WAIT(n)  asm volatile("cp.async.wait_group %0;" :: "n"(n) : "memory")
#define LDSM4(r0,r1,r2,r3,addr) \
    asm volatile("ldmatrix.sync.aligned.m8n8.x4.shared.b16 {%0,%1,%2,%3}, [%4];" \
        : "=r"(r0),"=r"(r1),"=r"(r2),"=r"(r3) : "r"(addr))
#define MMA16816(c, a, b0, b1) \
    asm volatile("mma.sync.aligned.m16n8k16.row.col.f32.f16.f16.f32 " \
        "{%0,%1,%2,%3}, {%4,%5,%6,%7}, {%8,%9}, {%0,%1,%2,%3};" \
        : "+f"((c)[0]), "+f"((c)[1]), "+f"((c)[2]), "+f"((c)[3]) \
        : "r"((a)[0]), "r"((a)[1]), "r"((a)[2]), "r"((a)[3]), "r"(b0), "r"(b1))

__device__ __forceinline__ uint32_t swz(uint32_t row, uint32_t byteoff) {
    uint32_t seg = (byteoff >> 4) ^ (row & 7);
    return row * 128 + (seg << 4) + (byteoff & 15);
}

// ------------------------- merged converts + counter reset -------------------
__global__ void convert_all_kernel(const float* __restrict__ x,
                                   const float* __restrict__ Wq,
                                   const float* __restrict__ Wk,
                                   const float* __restrict__ Wv) {
    if (blockIdx.x == 0 && threadIdx.x == 0) {
        g_ctr_qkv = 0; g_ctr_sco = 0; g_ctr_pv = 0;
    }
    if (blockIdx.x < 8192) {
        size_t i = (size_t)blockIdx.x * 256 + threadIdx.x;
        float4 v = ((const float4*)x)[i];
        __half2 h0 = __floats2half2_rn(v.x, v.y);
        __half2 h1 = __floats2half2_rn(v.z, v.w);
        ((uint2*)g_xh)[i] = make_uint2(*(uint32_t*)&h0, *(uint32_t*)&h1);
    } else {
        __shared__ float tile[32][33];
        int wb = blockIdx.x - 8192;
        const int sel = wb >> 10;
        wb &= 1023;
        const float* W = (sel == 0) ? Wq : (sel == 1) ? Wk : Wv;
        int bx = (wb & 31) * 32, by = (wb >> 5) * 32;
        int tx = threadIdx.x & 31, ty = threadIdx.x >> 5;
#pragma unroll
        for (int r = 0; r < 4; r++)
            tile[ty + 8*r][tx] = W[(size_t)(by + ty + 8*r) * CC + bx + tx];
        __syncthreads();
        __half* dst = g_wt + (size_t)sel * CC * CC;
#pragma unroll
        for (int r = 0; r < 4; r++)
            dst[(size_t)(bx + ty + 8*r) * CC + by + tx] = __float2half(tile[tx][ty + 8*r]);
    }
}

// ------------------------- pipelined MMA mainloop (128x128, BK=64) -----------
__device__ __forceinline__ void issue_stage(uint32_t sm, int stage,
                                            const __half* __restrict__ Ag, int lda,
                                            const __half* __restrict__ Bg, int ldb, int k0) {
    const int tid = threadIdx.x;
    uint32_t sb = sm + stage * STAGE_B;
#pragma unroll
    for (int i = 0; i < 4; i++) {
        int c = tid + i * 256;
        int row = c >> 3, seg = c & 7;
        CP_ASYNC16(sb + swz(row, seg * 16), Ag + (size_t)row * lda + k0 + seg * 8);
    }
#pragma unroll
    for (int i = 0; i < 4; i++) {
        int c = tid + i * 256;
        int row = c >> 3, seg = c & 7;
        CP_ASYNC16(sb + 16384 + swz(row, seg * 16), Bg + (size_t)row * ldb + k0 + seg * 8);
    }
}

// acc[2][8][4]: warp tile 32(m) x 64(n); 8 warps as 4x2 (m x n)
__device__ __forceinline__ void gemm_mainloop(uint32_t sm,
                                              const __half* __restrict__ Ag, int lda,
                                              const __half* __restrict__ Bg, int ldb,
                                              int nK, float acc[2][8][4]) {
    const int tid  = threadIdx.x;
    const int warp = tid >> 5, lane = tid & 31;
    const int m0w = (warp & 3) * 32, n0w = (warp >> 2) * 64;

    const uint32_t aK0 = swz(m0w + (lane & 15), ((lane >> 4) & 1) * 16);
    const uint32_t bK0 = 16384 + swz(n0w + ((lane >> 4) & 1) * 8 + (lane & 7),
                                     ((lane >> 3) & 1) * 16);

    issue_stage(sm, 0, Ag, lda, Bg, ldb, 0);  CP_COMMIT();
    issue_stage(sm, 1, Ag, lda, Bg, ldb, 64); CP_COMMIT();

    for (int ks = 0; ks < nK; ks++) {
        CP_WAIT(1);
        __syncthreads();
        if (ks + 2 < nK) issue_stage(sm, (ks + 2) % 3, Ag, lda, Bg, ldb, (ks + 2) * 64);
        CP_COMMIT();

        const uint32_t so = sm + (ks % 3) * STAGE_B;
        const uint32_t ab = so + aK0, bb = so + bK0;
#pragma unroll
        for (int kk = 0; kk < 4; kk++) {
            uint32_t a[2][4], b[4][4];
            const uint32_t x = (uint32_t)(kk << 5);
#pragma unroll
            for (int mt = 0; mt < 2; mt++)
                LDSM4(a[mt][0], a[mt][1], a[mt][2], a[mt][3], (ab ^ x) + mt * 2048);
#pragma unroll
            for (int n16 = 0; n16 < 4; n16++)
                LDSM4(b[n16][0], b[n16][1], b[n16][2], b[n16][3], (bb ^ x) + n16 * 2048);
#pragma unroll
            for (int mt = 0; mt < 2; mt++)
#pragma unroll
                for (int n16 = 0; n16 < 4; n16++) {
                    MMA16816(acc[mt][2*n16],     a[mt], b[n16][0], b[n16][1]);
                    MMA16816(acc[mt][2*n16 + 1], a[mt], b[n16][2], b[n16][3]);
                }
        }
    }
    CP_WAIT(0);
    __syncthreads();
}

#define EPI_COORDS() \
    const int warp = threadIdx.x >> 5, lane = threadIdx.x & 31; \
    const int m0w = (warp & 3) * 32, n0w = (warp >> 2) * 64; \
    const int gm = lane >> 2, np = (lane & 3) * 2;

#define ACC_INIT() \
    float acc[2][8][4]; \
    _Pragma("unroll") for (int i = 0; i < 2; i++) \
    _Pragma("unroll") for (int j = 0; j < 8; j++) \
    _Pragma("unroll") for (int q = 0; q < 4; q++) acc[i][j][q] = 0.f;

#define SMEM_ALIGN128() \
    extern __shared__ char dynsm[]; \
    uint32_t sm = (smem_u32(dynsm) + 127u) & ~127u;

#define STEAL(ctr, s_tile) \
    do { if (threadIdx.x == 0) s_tile = atomicAdd(&ctr, 1u); __syncthreads(); } while (0)

// ------------------------- persistent fused QKV projection -------------------
__global__ __launch_bounds__(NTH, 2)
void qkv_mma_kernel(const float* __restrict__ bq, const float* __restrict__ bk,
                    const float* __restrict__ bv) {
    SMEM_ALIGN128();
    __shared__ unsigned int s_tile;
    for (;;) {
        STEAL(g_ctr_qkv, s_tile);
        const unsigned int t = s_tile;
        if (t >= NT_QKV) return;
        const int bx = (int)(t % 24), by = (int)(t / 24);
        const int row0 = by * 128, col0 = bx * 128;
        const int sel = bx >> 3;
        const int vcol0 = col0 & 1023;
        const float* bias = (sel == 0) ? bq : (sel == 1) ? bk : bv;
        const float mul = (sel == 0) ? SCALE : 1.0f;

        ACC_INIT();
        const __half* Ag = g_xh + (size_t)row0 * CC;
        const __half* Bg = g_wt + (size_t)col0 * CC;
        gemm_mainloop(sm, Ag, CC, Bg, CC, CC / 64, acc);

        EPI_COORDS();
        if (sel != 2) {
            __half* O = (sel == 0 ? g_qh : g_kh);
#pragma unroll
            for (int mt = 0; mt < 2; mt++)
#pragma unroll
                for (int nt = 0; nt < 8; nt++) {
                    int n = n0w + nt * 8 + np;
                    float b0 = __ldg(bias + vcol0 + n), b1 = __ldg(bias + vcol0 + n + 1);
                    int m = m0w + mt * 16 + gm;
                    __half2 h0 = __floats2half2_rn((acc[mt][nt][0] + b0) * mul,
                                                   (acc[mt][nt][1] + b1) * mul);
                    __half2 h1 = __floats2half2_rn((acc[mt][nt][2] + b0) * mul,
                                                   (acc[mt][nt][3] + b1) * mul);
                    *(uint32_t*)(O + (size_t)(row0 + m) * CC + vcol0 + n)     = *(uint32_t*)&h0;
                    *(uint32_t*)(O + (size_t)(row0 + m + 8) * CC + vcol0 + n) = *(uint32_t*)&h1;
                }
        } else {
            __half* stage = (__half*)dynsm;      // [128][136]
#pragma unroll
            for (int mt = 0; mt < 2; mt++)
#pragma unroll
                for (int nt = 0; nt < 8; nt++) {
                    int n = n0w + nt * 8 + np;
                    float b0 = __ldg(bias + vcol0 + n), b1 = __ldg(bias + vcol0 + n + 1);
                    int m = m0w + mt * 16 + gm;
                    stage[(size_t)n * 136 + m]           = __float2half(acc[mt][nt][0] + b0);
                    stage[(size_t)(n + 1) * 136 + m]     = __float2half(acc[mt][nt][1] + b1);
                    stage[(size_t)n * 136 + m + 8]       = __float2half(acc[mt][nt][2] + b0);
                    stage[(size_t)(n + 1) * 136 + m + 8] = __float2half(acc[mt][nt][3] + b1);
                }
            __syncthreads();
            const int z = row0 >> 11, tok0 = row0 & (TT - 1);
            const int r = threadIdx.x >> 1, part = (threadIdx.x & 1) * 8;
            const uint4* srcrow = (const uint4*)(stage + (size_t)r * 136);
            __half* dst = g_vt + ((size_t)z * CC + vcol0 + r) * TT + tok0;
#pragma unroll
            for (int i = 0; i < 8; i++)
                ((uint4*)dst)[part + i] = srcrow[part + i];
        }
        __syncthreads();
    }
}

// ------------------------- persistent scores (triangular) --------------------
__global__ __launch_bounds__(NTH, 2)
void scores_mma_kernel() {
    SMEM_ALIGN128();
    __shared__ unsigned int s_tile;
    for (;;) {
        STEAL(g_ctr_sco, s_tile);
        const unsigned int t = s_tile;
        if (t >= NT_SCO) return;
        const int z = (int)(t & 3);
        const int idx = (int)(t >> 2);
        int by = (int)((sqrtf(8.0f * idx + 1.0f) - 1.0f) * 0.5f);
        while ((by + 1) * (by + 2) / 2 <= idx) by++;
        while (by * (by + 1) / 2 > idx) by--;
        const int bx = idx - by * (by + 1) / 2;
        const int t0 = by * 128, s0 = bx * 128;

        ACC_INIT();
        const __half* Ag = g_qh + ((size_t)z * TT + t0) * CC;
        const __half* Bg = g_kh + ((size_t)z * TT + s0) * CC;
        gemm_mainloop(sm, Ag, CC, Bg, CC, CC / 64, acc);

        EPI_COORDS();
        float* S = g_s + ((size_t)z * TT + t0) * TT + s0;
#pragma unroll
        for (int mt = 0; mt < 2; mt++)
#pragma unroll
            for (int nt = 0; nt < 8; nt++) {
                int m = m0w + mt * 16 + gm, n = n0w + nt * 8 + np;
                *(float2*)(S + (size_t)m * TT + n)       = make_float2(acc[mt][nt][0], acc[mt][nt][1]);
                *(float2*)(S + (size_t)(m + 8) * TT + n) = make_float2(acc[mt][nt][2], acc[mt][nt][3]);
            }
        __syncthreads();
    }
}

// ------------------------- softmax: warp per row, register-resident ----------
__global__ __launch_bounds__(256)
void softmax_kernel() {
    const int warp = threadIdx.x >> 5, lane = threadIdx.x & 31;
    const int row = blockIdx.x * 8 + warp;
    const int z = row >> 11;
    const int t = row & (TT - 1);
    const size_t off = ((size_t)z * TT + t) * TT;
    const float4* __restrict__ S4 = (const float4*)(g_s + off);
    const int n = t + 1;                       // valid elements
    const int nch = (n + 3) >> 2;              // float4 chunks with any valid data
    const int zEnd = ((t >> 7) + 1) << 7;      // pad to 128-tile boundary
    const int wch = zEnd >> 2;                 // chunks to write

    float4 v[16];                              // row resident in registers
    float mx = -INFINITY;
#pragma unroll
    for (int j = 0; j < 16; j++) {
        const int c = lane + 32 * j;
        if (c < nch) {
            float4 vv = S4[c];
            const int base = c * 4;
            if (base + 3 >= n) {               // causal tail mask
                if (base + 1 >= n) vv.y = -INFINITY;
                if (base + 2 >= n) vv.z = -INFINITY;
                if (base + 3 >= n) vv.w = -INFINITY;
            }
            v[j] = vv;
            mx = fmaxf(mx, fmaxf(fmaxf(vv.x, vv.y), fmaxf(vv.z, vv.w)));
        } else {
            v[j] = make_float4(-INFINITY, -INFINITY, -INFINITY, -INFINITY);
        }
    }
#pragma unroll
    for (int o = 16; o > 0; o >>= 1)
        mx = fmaxf(mx, __shfl_xor_sync(0xFFFFFFFFu, mx, o));

    float sum = 0.f;
#pragma unroll
    for (int j = 0; j < 16; j++) {
        if (lane + 32 * j < nch) {
            float4 vv = v[j];
            vv.x = __expf(vv.x - mx); vv.y = __expf(vv.y - mx);
            vv.z = __expf(vv.z - mx); vv.w = __expf(vv.w - mx);
            v[j] = vv;
            sum += vv.x + vv.y + vv.z + vv.w;
        }
    }
#pragma unroll
    for (int o = 16; o > 0; o >>= 1)
        sum += __shfl_xor_sync(0xFFFFFFFFu, sum, o);
    const float inv = 1.f / sum;

    __half* P = g_ph + off;
#pragma unroll
    for (int j = 0; j < 16; j++) {
        const int c = lane + 32 * j;
        if (c < wch) {
            float4 vv = v[j];
            __half2 h0, h1;
            if (c < nch) {
                h0 = __floats2half2_rn(vv.x * inv, vv.y * inv);
                h1 = __floats2half2_rn(vv.z * inv, vv.w * inv);
                // components beyond n were exp(-inf)=0 already
            } else {
                h0 = __floats2half2_rn(0.f, 0.f);
                h1 = h0;
            }
            uint2 o2 = make_uint2(*(uint32_t*)&h0, *(uint32_t*)&h1);
            *(uint2*)(P + c * 4) = o2;
        }
    }
}

// ------------------------- persistent P @ V (heavy tiles first) --------------
__global__ __launch_bounds__(NTH, 2)
void pv_mma_kernel(float* __restrict__ Out) {
    SMEM_ALIGN128();
    __shared__ unsigned int s_tile;
    for (;;) {
        STEAL(g_ctr_pv, s_tile);
        const unsigned int t = s_tile;
        if (t >= NT_PV) return;
        const int by = 15 - (int)(t >> 5);
        const int z  = (int)((t >> 3) & 3);
        const int bx = (int)(t & 7);
        const int t0 = by * 128, c0 = bx * 128;

        ACC_INIT();
        const __half* Ag = g_ph + ((size_t)z * TT + t0) * TT;
        const __half* Bg = g_vt + ((size_t)z * CC + c0) * TT;
        gemm_mainloop(sm, Ag, TT, Bg, TT, (by + 1) * 2, acc);

        EPI_COORDS();
        float* O = Out + ((size_t)z * TT + t0) * CC + c0;
#pragma unroll
        for (int mt = 0; mt < 2; mt++)
#pragma unroll
            for (int nt = 0; nt < 8; nt++) {
                int m = m0w + mt * 16 + gm, n = n0w + nt * 8 + np;
                *(float2*)(O + (size_t)m * CC + n)       = make_float2(acc[mt][nt][0], acc[mt][nt][1]);
                *(float2*)(O + (size_t)(m + 8) * CC + n) = make_float2(acc[mt][nt][2], acc[mt][nt][3]);
            }
        __syncthreads();
    }
}

// ------------------------- launch: single stream, persistent grids -----------
extern "C" void kernel_launch(void* const* d_in, const int* in_sizes, int n_in,
                              void* d_out, int out_size) {
    const float* x  = (const float*)d_in[0];
    const float* Wq = (const float*)d_in[1];
    const float* bq = (const float*)d_in[2];
    const float* Wk = (const float*)d_in[3];
    const float* bk = (const float*)d_in[4];
    const float* Wv = (const float*)d_in[5];
    const float* bv = (const float*)d_in[6];
    float* out = (float*)d_out;

    cudaFuncSetAttribute(qkv_mma_kernel,    cudaFuncAttributeMaxDynamicSharedMemorySize, DYN_B);
    cudaFuncSetAttribute(scores_mma_kernel, cudaFuncAttributeMaxDynamicSharedMemorySize, DYN_B);
    cudaFuncSetAttribute(pv_mma_kernel,     cudaFuncAttributeMaxDynamicSharedMemorySize, DYN_B);

    convert_all_kernel<<<8192 + 3072, 256>>>(x, Wq, Wk, Wv);
    qkv_mma_kernel<<<NPERS, NTH, DYN_B>>>(bq, bk, bv);
    scores_mma_kernel<<<NPERS, NTH, DYN_B>>>();
    softmax_kernel<<<BB * TT / 8, 256>>>();
    pv_mma_kernel<<<NPERS, NTH, DYN_B>>>(out);
}

// round 16
// speedup vs baseline: 1.0389x; 1.0389x over previous
#include <cuda_runtime.h>
#include <cuda_fp16.h>
#include <cstdint>
#include <math.h>

#define BB 4
#define TT 2048
#define CC 1024
#define MTOT (BB*TT)
#define SCALE 0.03125f

#define NTH 256
#define STAGE_B 32768      // A 16KB (128x64) + B 16KB (128x64) per stage
#define STAGES 3
#define DYN_B (STAGES*STAGE_B + 128)
#define NPERS 296          // persistent CTAs (148 SMs x 2)

#define NT_QKV 1536        // 24 n-tiles x 64 m-tiles
#define NT_SCO 544         // 4 x 136 triangular
#define NT_SM  1024        // 4 x 16 row-blocks x 16 groups of 8 rows
#define NT_PV  512         // 4 x 16 x 8
#define NT_ATT (NT_SCO + NT_SM + NT_PV)   // 2080

// ------------------------- device scratch (no allocs) -----------------------
__device__ __half g_xh[MTOT*CC];
__device__ __half g_wt[3*CC*CC];                    // W^T fp16 [sel*1024+n][k]
__device__ __half g_qh[MTOT*CC];                    // q * SCALE
__device__ __half g_kh[MTOT*CC];
__device__ __half g_vt[(size_t)BB*CC*TT];           // V^T per batch [c][token]
__device__ float  g_s[(size_t)BB*TT*TT];
__device__ __half g_ph[(size_t)BB*TT*TT];
__device__ unsigned int g_ctr_qkv, g_ctr_att;
__device__ unsigned int g_done_sco[64];             // [z*16+by] -> by+1 when ready
__device__ unsigned int g_done_sm[64];              // [z*16+by] -> 16 when ready

// ------------------------- ptx helpers --------------------------------------
__device__ __forceinline__ uint32_t smem_u32(const void* p) {
    uint32_t a;
    asm("{ .reg .u64 t; cvta.to.shared.u64 t, %1; cvt.u32.u64 %0, t; }" : "=r"(a) : "l"(p));
    return a;
}
#define CP_ASYNC16(dst, src) \
    asm volatile("cp.async.cg.shared.global [%0], [%1], 16;" :: "r"(dst), "l"(src))
#define CP_COMMIT() asm volatile("cp.async.commit_group;" ::: "memory")
#define CP_WAIT(n)  asm volatile("cp.async.wait_group %0;" :: "n"(n) : "memory")
#define LDSM4(r0,r1,r2,r3,addr) \
    asm volatile("ldmatrix.sync.aligned.m8n8.x4.shared.b16 {%0,%1,%2,%3}, [%4];" \
        : "=r"(r0),"=r"(r1),"=r"(r2),"=r"(r3) : "r"(addr))
#define MMA16816(c, a, b0, b1) \
    asm volatile("mma.sync.aligned.m16n8k16.row.col.f32.f16.f16.f32 " \
        "{%0,%1,%2,%3}, {%4,%5,%6,%7}, {%8,%9}, {%0,%1,%2,%3};" \
        : "+f"((c)[0]), "+f"((c)[1]), "+f"((c)[2]), "+f"((c)[3]) \
        : "r"((a)[0]), "r"((a)[1]), "r"((a)[2]), "r"((a)[3]), "r"(b0), "r"(b1))

__device__ __forceinline__ uint32_t swz(uint32_t row, uint32_t byteoff) {
    uint32_t seg = (byteoff >> 4) ^ (row & 7);
    return row * 128 + (seg << 4) + (byteoff & 15);
}

// ------------------------- merged converts + control reset -------------------
__global__ void convert_all_kernel(const float* __restrict__ x,
                                   const float* __restrict__ Wq,
                                   const float* __restrict__ Wk,
                                   const float* __restrict__ Wv) {
    if (blockIdx.x == 0 && threadIdx.x < 64) {
        if (threadIdx.x == 0) { g_ctr_qkv = 0; g_ctr_att = 0; }
        g_done_sco[threadIdx.x] = 0;
        g_done_sm[threadIdx.x] = 0;
    }
    if (blockIdx.x < 8192) {
        size_t i = (size_t)blockIdx.x * 256 + threadIdx.x;
        float4 v = ((const float4*)x)[i];
        __half2 h0 = __floats2half2_rn(v.x, v.y);
        __half2 h1 = __floats2half2_rn(v.z, v.w);
        ((uint2*)g_xh)[i] = make_uint2(*(uint32_t*)&h0, *(uint32_t*)&h1);
    } else {
        __shared__ float tile[32][33];
        int wb = blockIdx.x - 8192;
        const int sel = wb >> 10;
        wb &= 1023;
        const float* W = (sel == 0) ? Wq : (sel == 1) ? Wk : Wv;
        int bx = (wb & 31) * 32, by = (wb >> 5) * 32;
        int tx = threadIdx.x & 31, ty = threadIdx.x >> 5;
#pragma unroll
        for (int r = 0; r < 4; r++)
            tile[ty + 8*r][tx] = W[(size_t)(by + ty + 8*r) * CC + bx + tx];
        __syncthreads();
        __half* dst = g_wt + (size_t)sel * CC * CC;
#pragma unroll
        for (int r = 0; r < 4; r++)
            dst[(size_t)(bx + ty + 8*r) * CC + by + tx] = __float2half(tile[tx][ty + 8*r]);
    }
}

// ------------------------- pipelined MMA mainloop (128x128, BK=64) -----------
__device__ __forceinline__ void issue_stage(uint32_t sm, int stage,
                                            const __half* __restrict__ Ag, int lda,
                                            const __half* __restrict__ Bg, int ldb, int k0) {
    const int tid = threadIdx.x;
    uint32_t sb = sm + stage * STAGE_B;
#pragma unroll
    for (int i = 0; i < 4; i++) {
        int c = tid + i * 256;
        int row = c >> 3, seg = c & 7;
        CP_ASYNC16(sb + swz(row, seg * 16), Ag + (size_t)row * lda + k0 + seg * 8);
    }
#pragma unroll
    for (int i = 0; i < 4; i++) {
        int c = tid + i * 256;
        int row = c >> 3, seg = c & 7;
        CP_ASYNC16(sb + 16384 + swz(row, seg * 16), Bg + (size_t)row * ldb + k0 + seg * 8);
    }
}

// acc[2][8][4]: warp tile 32(m) x 64(n); 8 warps as 4x2 (m x n)
__device__ __forceinline__ void gemm_mainloop(uint32_t sm,
                                              const __half* __restrict__ Ag, int lda,
                                              const __half* __restrict__ Bg, int ldb,
                                              int nK, float acc[2][8][4]) {
    const int tid  = threadIdx.x;
    const int warp = tid >> 5, lane = tid & 31;
    const int m0w = (warp & 3) * 32, n0w = (warp >> 2) * 64;

    const uint32_t aK0 = swz(m0w + (lane & 15), ((lane >> 4) & 1) * 16);
    const uint32_t bK0 = 16384 + swz(n0w + ((lane >> 4) & 1) * 8 + (lane & 7),
                                     ((lane >> 3) & 1) * 16);

    issue_stage(sm, 0, Ag, lda, Bg, ldb, 0);  CP_COMMIT();
    issue_stage(sm, 1, Ag, lda, Bg, ldb, 64); CP_COMMIT();

    for (int ks = 0; ks < nK; ks++) {
        CP_WAIT(1);
        __syncthreads();
        if (ks + 2 < nK) issue_stage(sm, (ks + 2) % 3, Ag, lda, Bg, ldb, (ks + 2) * 64);
        CP_COMMIT();

        const uint32_t so = sm + (ks % 3) * STAGE_B;
        const uint32_t ab = so + aK0, bb = so + bK0;
#pragma unroll
        for (int kk = 0; kk < 4; kk++) {
            uint32_t a[2][4], b[4][4];
            const uint32_t x = (uint32_t)(kk << 5);
#pragma unroll
            for (int mt = 0; mt < 2; mt++)
                LDSM4(a[mt][0], a[mt][1], a[mt][2], a[mt][3], (ab ^ x) + mt * 2048);
#pragma unroll
            for (int n16 = 0; n16 < 4; n16++)
                LDSM4(b[n16][0], b[n16][1], b[n16][2], b[n16][3], (bb ^ x) + n16 * 2048);
#pragma unroll
            for (int mt = 0; mt < 2; mt++)
#pragma unroll
                for (int n16 = 0; n16 < 4; n16++) {
                    MMA16816(acc[mt][2*n16],     a[mt], b[n16][0], b[n16][1]);
                    MMA16816(acc[mt][2*n16 + 1], a[mt], b[n16][2], b[n16][3]);
                }
        }
    }
    CP_WAIT(0);
    __syncthreads();
}

#define EPI_COORDS() \
    const int warp = threadIdx.x >> 5, lane = threadIdx.x & 31; \
    const int m0w = (warp & 3) * 32, n0w = (warp >> 2) * 64; \
    const int gm = lane >> 2, np = (lane & 3) * 2;

#define ACC_INIT() \
    float acc[2][8][4]; \
    _Pragma("unroll") for (int i = 0; i < 2; i++) \
    _Pragma("unroll") for (int j = 0; j < 8; j++) \
    _Pragma("unroll") for (int q = 0; q < 4; q++) acc[i][j][q] = 0.f;

#define SMEM_ALIGN128() \
    extern __shared__ char dynsm[]; \
    uint32_t sm = (smem_u32(dynsm) + 127u) & ~127u;

#define STEAL(ctr, s_tile) \
    do { if (threadIdx.x == 0) s_tile = atomicAdd(&ctr, 1u); __syncthreads(); } while (0)

// block-wide release: all writes of this tile visible, then bump flag
#define RELEASE(flagp) \
    do { __threadfence(); __syncthreads(); \
         if (threadIdx.x == 0) atomicAdd((flagp), 1u); } while (0)

// block-wide acquire: wait until *flagp >= need
#define ACQUIRE(flagp, need) \
    do { if (threadIdx.x == 0) { \
             while (*(volatile unsigned int*)(flagp) < (unsigned)(need)) __nanosleep(128); \
         } __syncthreads(); } while (0)

// ------------------------- persistent fused QKV projection -------------------
__global__ __launch_bounds__(NTH, 2)
void qkv_mma_kernel(const float* __restrict__ bq, const float* __restrict__ bk,
                    const float* __restrict__ bv) {
    SMEM_ALIGN128();
    __shared__ unsigned int s_tile;
    for (;;) {
        STEAL(g_ctr_qkv, s_tile);
        const unsigned int t = s_tile;
        if (t >= NT_QKV) return;
        const int bx = (int)(t % 24), by = (int)(t / 24);
        const int row0 = by * 128, col0 = bx * 128;
        const int sel = bx >> 3;
        const int vcol0 = col0 & 1023;
        const float* bias = (sel == 0) ? bq : (sel == 1) ? bk : bv;
        const float mul = (sel == 0) ? SCALE : 1.0f;

        ACC_INIT();
        const __half* Ag = g_xh + (size_t)row0 * CC;
        const __half* Bg = g_wt + (size_t)col0 * CC;
        gemm_mainloop(sm, Ag, CC, Bg, CC, CC / 64, acc);

        EPI_COORDS();
        if (sel != 2) {
            __half* O = (sel == 0 ? g_qh : g_kh);
#pragma unroll
            for (int mt = 0; mt < 2; mt++)
#pragma unroll
                for (int nt = 0; nt < 8; nt++) {
                    int n = n0w + nt * 8 + np;
                    float b0 = __ldg(bias + vcol0 + n), b1 = __ldg(bias + vcol0 + n + 1);
                    int m = m0w + mt * 16 + gm;
                    __half2 h0 = __floats2half2_rn((acc[mt][nt][0] + b0) * mul,
                                                   (acc[mt][nt][1] + b1) * mul);
                    __half2 h1 = __floats2half2_rn((acc[mt][nt][2] + b0) * mul,
                                                   (acc[mt][nt][3] + b1) * mul);
                    *(uint32_t*)(O + (size_t)(row0 + m) * CC + vcol0 + n)     = *(uint32_t*)&h0;
                    *(uint32_t*)(O + (size_t)(row0 + m + 8) * CC + vcol0 + n) = *(uint32_t*)&h1;
                }
        } else {
            __half* stage = (__half*)dynsm;      // [128][136]
#pragma unroll
            for (int mt = 0; mt < 2; mt++)
#pragma unroll
                for (int nt = 0; nt < 8; nt++) {
                    int n = n0w + nt * 8 + np;
                    float b0 = __ldg(bias + vcol0 + n), b1 = __ldg(bias + vcol0 + n + 1);
                    int m = m0w + mt * 16 + gm;
                    stage[(size_t)n * 136 + m]           = __float2half(acc[mt][nt][0] + b0);
                    stage[(size_t)(n + 1) * 136 + m]     = __float2half(acc[mt][nt][1] + b1);
                    stage[(size_t)n * 136 + m + 8]       = __float2half(acc[mt][nt][2] + b0);
                    stage[(size_t)(n + 1) * 136 + m + 8] = __float2half(acc[mt][nt][3] + b1);
                }
            __syncthreads();
            const int z = row0 >> 11, tok0 = row0 & (TT - 1);
            const int r = threadIdx.x >> 1, part = (threadIdx.x & 1) * 8;
            const uint4* srcrow = (const uint4*)(stage + (size_t)r * 136);
            __half* dst = g_vt + ((size_t)z * CC + vcol0 + r) * TT + tok0;
#pragma unroll
            for (int i = 0; i < 8; i++)
                ((uint4*)dst)[part + i] = srcrow[part + i];
        }
        __syncthreads();
    }
}

// ------------------------- fused scores -> softmax -> PV ---------------------
__global__ __launch_bounds__(NTH, 2)
void attn_kernel(float* __restrict__ Out) {
    SMEM_ALIGN128();
    __shared__ unsigned int s_tile;
    for (;;) {
        STEAL(g_ctr_att, s_tile);
        const unsigned int t = s_tile;
        if (t >= NT_ATT) return;

        if (t < NT_SCO) {
            // ---- scores tile, by descending (diagonal row-blocks first) ----
            const int z = (int)(t & 3);
            const int idx = 135 - (int)(t >> 2);
            int by = (int)((sqrtf(8.0f * idx + 1.0f) - 1.0f) * 0.5f);
            while ((by + 1) * (by + 2) / 2 <= idx) by++;
            while (by * (by + 1) / 2 > idx) by--;
            const int bx = idx - by * (by + 1) / 2;
            const int t0 = by * 128, s0 = bx * 128;

            ACC_INIT();
            const __half* Ag = g_qh + ((size_t)z * TT + t0) * CC;
            const __half* Bg = g_kh + ((size_t)z * TT + s0) * CC;
            gemm_mainloop(sm, Ag, CC, Bg, CC, CC / 64, acc);

            EPI_COORDS();
            float* S = g_s + ((size_t)z * TT + t0) * TT + s0;
#pragma unroll
            for (int mt = 0; mt < 2; mt++)
#pragma unroll
                for (int nt = 0; nt < 8; nt++) {
                    int m = m0w + mt * 16 + gm, n = n0w + nt * 8 + np;
                    *(float2*)(S + (size_t)m * TT + n)       = make_float2(acc[mt][nt][0], acc[mt][nt][1]);
                    *(float2*)(S + (size_t)(m + 8) * TT + n) = make_float2(acc[mt][nt][2], acc[mt][nt][3]);
                }
            RELEASE(&g_done_sco[z * 16 + by]);
        } else if (t < NT_SCO + NT_SM) {
            // ---- softmax group: 8 rows, smem staging (round-14 algorithm) ----
            const int j = (int)(t - NT_SCO);
            const int by = 15 - (j >> 6);
            const int z  = (j >> 4) & 3;
            const int grp = j & 15;
            ACQUIRE(&g_done_sco[z * 16 + by], by + 1);

            float* shall = (float*)dynsm;        // 8 rows x 2048 floats = 64KB
            const int warp = threadIdx.x >> 5, lane = threadIdx.x & 31;
            const int trow = by * 128 + grp * 8 + warp;
            const size_t off = ((size_t)z * TT + trow) * TT;
            const float4* __restrict__ S4 = (const float4*)(g_s + off);
            float* sh = shall + warp * TT;
            const int n = trow + 1;
            const int nch = (n + 3) >> 2;

            float mx = -INFINITY;
            for (int c = lane; c < nch; c += 32) {
                float4 v = S4[c];
                int base = c * 4;
                if (base + 3 >= n) {
                    if (base + 1 >= n) v.y = -INFINITY;
                    if (base + 2 >= n) v.z = -INFINITY;
                    if (base + 3 >= n) v.w = -INFINITY;
                }
                ((float4*)sh)[c] = v;
                mx = fmaxf(mx, fmaxf(fmaxf(v.x, v.y), fmaxf(v.z, v.w)));
            }
#pragma unroll
            for (int o = 16; o > 0; o >>= 1)
                mx = fmaxf(mx, __shfl_xor_sync(0xFFFFFFFFu, mx, o));

            float sum = 0.f;
            for (int c = lane; c < nch; c += 32) {
                float4 v = ((float4*)sh)[c];
                v.x = __expf(v.x - mx); v.y = __expf(v.y - mx);
                v.z = __expf(v.z - mx); v.w = __expf(v.w - mx);
                ((float4*)sh)[c] = v;
                sum += v.x + v.y + v.z + v.w;
            }
#pragma unroll
            for (int o = 16; o > 0; o >>= 1)
                sum += __shfl_xor_sync(0xFFFFFFFFu, sum, o);
            const float inv = 1.f / sum;
            __syncwarp();

            const int zEnd = ((trow >> 7) + 1) << 7;
            __half* P = g_ph + off;
            for (int c = lane; c < (zEnd >> 3); c += 32) {
                int i0 = c * 8;
                __half h[8];
#pragma unroll
                for (int jj = 0; jj < 8; jj++) {
                    int idx2 = i0 + jj;
                    h[jj] = __float2half((idx2 < n) ? sh[idx2] * inv : 0.f);
                }
                *(uint4*)(P + i0) = *(uint4*)h;
            }
            RELEASE(&g_done_sm[z * 16 + by]);
        } else {
            // ---- PV tile (heavy-first) ----
            const int p = (int)(t - NT_SCO - NT_SM);
            const int by = 15 - (p >> 5);
            const int z  = (p >> 3) & 3;
            const int bx = p & 7;
            ACQUIRE(&g_done_sm[z * 16 + by], 16);

            const int t0 = by * 128, c0 = bx * 128;
            ACC_INIT();
            const __half* Ag = g_ph + ((size_t)z * TT + t0) * TT;
            const __half* Bg = g_vt + ((size_t)z * CC + c0) * TT;
            gemm_mainloop(sm, Ag, TT, Bg, TT, (by + 1) * 2, acc);

            EPI_COORDS();
            float* O = Out + ((size_t)z * TT + t0) * CC + c0;
#pragma unroll
            for (int mt = 0; mt < 2; mt++)
#pragma unroll
                for (int nt = 0; nt < 8; nt++) {
                    int m = m0w + mt * 16 + gm, n = n0w + nt * 8 + np;
                    *(float2*)(O + (size_t)m * CC + n)       = make_float2(acc[mt][nt][0], acc[mt][nt][1]);
                    *(float2*)(O + (size_t)(m + 8) * CC + n) = make_float2(acc[mt][nt][2], acc[mt][nt][3]);
                }
        }
        __syncthreads();   // quiesce smem / s_tile before next steal
    }
}

// ------------------------- launch --------------------------------------------
extern "C" void kernel_launch(void* const* d_in, const int* in_sizes, int n_in,
                              void* d_out, int out_size) {
    const float* x  = (const float*)d_in[0];
    const float* Wq = (const float*)d_in[1];
    const float* bq = (const float*)d_in[2];
    const float* Wk = (const float*)d_in[3];
    const float* bk = (const float*)d_in[4];
    const float* Wv = (const float*)d_in[5];
    const float* bv = (const float*)d_in[6];
    float* out = (float*)d_out;

    cudaFuncSetAttribute(qkv_mma_kernel, cudaFuncAttributeMaxDynamicSharedMemorySize, DYN_B);
    cudaFuncSetAttribute(attn_kernel,    cudaFuncAttributeMaxDynamicSharedMemorySize, DYN_B);

    convert_all_kernel<<<8192 + 3072, 256>>>(x, Wq, Wk, Wv);
    qkv_mma_kernel<<<NPERS, NTH, DYN_B>>>(bq, bk, bv);
    attn_kernel<<<NPERS, NTH, DYN_B>>>(out);
}

// round 17
// speedup vs baseline: 1.0791x; 1.0387x over previous
#include <cuda_runtime.h>
#include <cuda_fp16.h>
#include <cstdint>
#include <math.h>

#define BB 4
#define TT 2048
#define CC 1024
#define MTOT (BB*TT)
#define SCALE 0.03125f

#define NTH 256
#define STAGE_B 32768      // A 16KB (128x64) + B 16KB (128x64) per stage
#define STAGES 3
#define DYN_B (STAGES*STAGE_B + 128)
#define NPERS 296          // persistent CTAs (148 SMs x 2)

#define NT_QKV 1536        // 24 n-tiles x 64 m-tiles
#define NT_SCO 544         // 4 x 136 triangular
#define NT_SM  1024        // 4 x 16 row-blocks x 16 groups of 8 rows
#define NT_PV  512         // 4 x 16 x 8
#define OFF_SCO NT_QKV
#define OFF_SM  (NT_QKV + NT_SCO)
#define OFF_PV  (NT_QKV + NT_SCO + NT_SM)
#define NT_ALL  (NT_QKV + NT_SCO + NT_SM + NT_PV)   // 3616

// ------------------------- device scratch (no allocs) -----------------------
__device__ __half g_xh[MTOT*CC];
__device__ __half g_wt[3*CC*CC];                    // W^T fp16 [sel*1024+n][k]
__device__ __half g_qh[MTOT*CC];                    // q * SCALE
__device__ __half g_kh[MTOT*CC];
__device__ __half g_vt[(size_t)BB*CC*TT];           // V^T per batch [c][token]
__device__ float  g_s[(size_t)BB*TT*TT];
__device__ __half g_ph[(size_t)BB*TT*TT];
__device__ unsigned int g_ctr;
__device__ unsigned int g_done_q[64], g_done_k[64]; // per global m-tile -> 8
__device__ unsigned int g_done_v[32];               // [z*8+vcoltile] -> 16
__device__ unsigned int g_done_sco[64];             // [z*16+by] -> by+1
__device__ unsigned int g_done_sm[64];              // [z*16+by] -> 16

// ------------------------- ptx helpers --------------------------------------
__device__ __forceinline__ uint32_t smem_u32(const void* p) {
    uint32_t a;
    asm("{ .reg .u64 t; cvta.to.shared.u64 t, %1; cvt.u32.u64 %0, t; }" : "=r"(a) : "l"(p));
    return a;
}
#define CP_ASYNC16(dst, src) \
    asm volatile("cp.async.cg.shared.global [%0], [%1], 16;" :: "r"(dst), "l"(src))
#define CP_COMMIT() asm volatile("cp.async.commit_group;" ::: "memory")
#define CP_WAIT(n)  asm volatile("cp.async.wait_group %0;" :: "n"(n) : "memory")
#define LDSM4(r0,r1,r2,r3,addr) \
    asm volatile("ldmatrix.sync.aligned.m8n8.x4.shared.b16 {%0,%1,%2,%3}, [%4];" \
        : "=r"(r0),"=r"(r1),"=r"(r2),"=r"(r3) : "r"(addr))
#define MMA16816(c, a, b0, b1) \
    asm volatile("mma.sync.aligned.m16n8k16.row.col.f32.f16.f16.f32 " \
        "{%0,%1,%2,%3}, {%4,%5,%6,%7}, {%8,%9}, {%0,%1,%2,%3};" \
        : "+f"((c)[0]), "+f"((c)[1]), "+f"((c)[2]), "+f"((c)[3]) \
        : "r"((a)[0]), "r"((a)[1]), "r"((a)[2]), "r"((a)[3]), "r"(b0), "r"(b1))

__device__ __forceinline__ uint32_t swz(uint32_t row, uint32_t byteoff) {
    uint32_t seg = (byteoff >> 4) ^ (row & 7);
    return row * 128 + (seg << 4) + (byteoff & 15);
}

// ------------------------- merged converts + control reset -------------------
__global__ void convert_all_kernel(const float* __restrict__ x,
                                   const float* __restrict__ Wq,
                                   const float* __restrict__ Wk,
                                   const float* __restrict__ Wv) {
    if (blockIdx.x == 0 && threadIdx.x < 64) {
        if (threadIdx.x == 0) g_ctr = 0;
        g_done_q[threadIdx.x] = 0;
        g_done_k[threadIdx.x] = 0;
        if (threadIdx.x < 32) g_done_v[threadIdx.x] = 0;
        g_done_sco[threadIdx.x] = 0;
        g_done_sm[threadIdx.x] = 0;
    }
    if (blockIdx.x < 8192) {
        size_t i = (size_t)blockIdx.x * 256 + threadIdx.x;
        float4 v = ((const float4*)x)[i];
        __half2 h0 = __floats2half2_rn(v.x, v.y);
        __half2 h1 = __floats2half2_rn(v.z, v.w);
        ((uint2*)g_xh)[i] = make_uint2(*(uint32_t*)&h0, *(uint32_t*)&h1);
    } else {
        __shared__ float tile[32][33];
        int wb = blockIdx.x - 8192;
        const int sel = wb >> 10;
        wb &= 1023;
        const float* W = (sel == 0) ? Wq : (sel == 1) ? Wk : Wv;
        int bx = (wb & 31) * 32, by = (wb >> 5) * 32;
        int tx = threadIdx.x & 31, ty = threadIdx.x >> 5;
#pragma unroll
        for (int r = 0; r < 4; r++)
            tile[ty + 8*r][tx] = W[(size_t)(by + ty + 8*r) * CC + bx + tx];
        __syncthreads();
        __half* dst = g_wt + (size_t)sel * CC * CC;
#pragma unroll
        for (int r = 0; r < 4; r++)
            dst[(size_t)(bx + ty + 8*r) * CC + by + tx] = __float2half(tile[tx][ty + 8*r]);
    }
}

// ------------------------- pipelined MMA mainloop (128x128, BK=64) -----------
__device__ __forceinline__ void issue_stage(uint32_t sm, int stage,
                                            const __half* __restrict__ Ag, int lda,
                                            const __half* __restrict__ Bg, int ldb, int k0) {
    const int tid = threadIdx.x;
    uint32_t sb = sm + stage * STAGE_B;
#pragma unroll
    for (int i = 0; i < 4; i++) {
        int c = tid + i * 256;
        int row = c >> 3, seg = c & 7;
        CP_ASYNC16(sb + swz(row, seg * 16), Ag + (size_t)row * lda + k0 + seg * 8);
    }
#pragma unroll
    for (int i = 0; i < 4; i++) {
        int c = tid + i * 256;
        int row = c >> 3, seg = c & 7;
        CP_ASYNC16(sb + 16384 + swz(row, seg * 16), Bg + (size_t)row * ldb + k0 + seg * 8);
    }
}

// acc[2][8][4]: warp tile 32(m) x 64(n); 8 warps as 4x2 (m x n)
__device__ __forceinline__ void gemm_mainloop(uint32_t sm,
                                              const __half* __restrict__ Ag, int lda,
                                              const __half* __restrict__ Bg, int ldb,
                                              int nK, float acc[2][8][4]) {
    const int tid  = threadIdx.x;
    const int warp = tid >> 5, lane = tid & 31;
    const int m0w = (warp & 3) * 32, n0w = (warp >> 2) * 64;

    const uint32_t aK0 = swz(m0w + (lane & 15), ((lane >> 4) & 1) * 16);
    const uint32_t bK0 = 16384 + swz(n0w + ((lane >> 4) & 1) * 8 + (lane & 7),
                                     ((lane >> 3) & 1) * 16);

    issue_stage(sm, 0, Ag, lda, Bg, ldb, 0);  CP_COMMIT();
    issue_stage(sm, 1, Ag, lda, Bg, ldb, 64); CP_COMMIT();

    for (int ks = 0; ks < nK; ks++) {
        CP_WAIT(1);
        __syncthreads();
        if (ks + 2 < nK) issue_stage(sm, (ks + 2) % 3, Ag, lda, Bg, ldb, (ks + 2) * 64);
        CP_COMMIT();

        const uint32_t so = sm + (ks % 3) * STAGE_B;
        const uint32_t ab = so + aK0, bb = so + bK0;
#pragma unroll
        for (int kk = 0; kk < 4; kk++) {
            uint32_t a[2][4], b[4][4];
            const uint32_t x = (uint32_t)(kk << 5);
#pragma unroll
            for (int mt = 0; mt < 2; mt++)
                LDSM4(a[mt][0], a[mt][1], a[mt][2], a[mt][3], (ab ^ x) + mt * 2048);
#pragma unroll
            for (int n16 = 0; n16 < 4; n16++)
                LDSM4(b[n16][0], b[n16][1], b[n16][2], b[n16][3], (bb ^ x) + n16 * 2048);
#pragma unroll
            for (int mt = 0; mt < 2; mt++)
#pragma unroll
                for (int n16 = 0; n16 < 4; n16++) {
                    MMA16816(acc[mt][2*n16],     a[mt], b[n16][0], b[n16][1]);
                    MMA16816(acc[mt][2*n16 + 1], a[mt], b[n16][2], b[n16][3]);
                }
        }
    }
    CP_WAIT(0);
    __syncthreads();
}

#define EPI_COORDS() \
    const int warp = threadIdx.x >> 5, lane = threadIdx.x & 31; \
    const int m0w = (warp & 3) * 32, n0w = (warp >> 2) * 64; \
    const int gm = lane >> 2, np = (lane & 3) * 2;

#define ACC_INIT() \
    float acc[2][8][4]; \
    _Pragma("unroll") for (int i = 0; i < 2; i++) \
    _Pragma("unroll") for (int j = 0; j < 8; j++) \
    _Pragma("unroll") for (int q = 0; q < 4; q++) acc[i][j][q] = 0.f;

#define STEAL(ctr, s_tile) \
    do { if (threadIdx.x == 0) s_tile = atomicAdd(&ctr, 1u); __syncthreads(); } while (0)

#define RELEASE(flagp) \
    do { __threadfence(); __syncthreads(); \
         if (threadIdx.x == 0) atomicAdd((flagp), 1u); } while (0)

#define ACQUIRE(flagp, need) \
    do { if (threadIdx.x == 0) { \
             while (*(volatile unsigned int*)(flagp) < (unsigned)(need)) __nanosleep(128); \
         } __syncthreads(); } while (0)

// ------------------------- fused QKV -> scores -> softmax -> PV --------------
__global__ __launch_bounds__(NTH, 2)
void mega_kernel(const float* __restrict__ bq, const float* __restrict__ bk,
                 const float* __restrict__ bv, float* __restrict__ Out) {
    extern __shared__ char dynsm[];
    uint32_t sm = (smem_u32(dynsm) + 127u) & ~127u;
    __shared__ unsigned int s_tile;
    for (;;) {
        STEAL(g_ctr, s_tile);
        const unsigned int t = s_tile;
        if (t >= NT_ALL) return;

        if (t < NT_QKV) {
            // ---- QKV projection tile ----
            const int bx = (int)(t % 24), by = (int)(t / 24);   // m-tiles ascending
            const int row0 = by * 128, col0 = bx * 128;
            const int sel = bx >> 3;
            const int vcol0 = col0 & 1023;
            const float* bias = (sel == 0) ? bq : (sel == 1) ? bk : bv;
            const float mul = (sel == 0) ? SCALE : 1.0f;

            ACC_INIT();
            const __half* Ag = g_xh + (size_t)row0 * CC;
            const __half* Bg = g_wt + (size_t)col0 * CC;
            gemm_mainloop(sm, Ag, CC, Bg, CC, CC / 64, acc);

            EPI_COORDS();
            if (sel != 2) {
                __half* O = (sel == 0 ? g_qh : g_kh);
#pragma unroll
                for (int mt = 0; mt < 2; mt++)
#pragma unroll
                    for (int nt = 0; nt < 8; nt++) {
                        int n = n0w + nt * 8 + np;
                        float b0 = __ldg(bias + vcol0 + n), b1 = __ldg(bias + vcol0 + n + 1);
                        int m = m0w + mt * 16 + gm;
                        __half2 h0 = __floats2half2_rn((acc[mt][nt][0] + b0) * mul,
                                                       (acc[mt][nt][1] + b1) * mul);
                        __half2 h1 = __floats2half2_rn((acc[mt][nt][2] + b0) * mul,
                                                       (acc[mt][nt][3] + b1) * mul);
                        *(uint32_t*)(O + (size_t)(row0 + m) * CC + vcol0 + n)     = *(uint32_t*)&h0;
                        *(uint32_t*)(O + (size_t)(row0 + m + 8) * CC + vcol0 + n) = *(uint32_t*)&h1;
                    }
                RELEASE((sel == 0) ? &g_done_q[by] : &g_done_k[by]);
            } else {
                __half* stage = (__half*)dynsm;      // [128][136]
#pragma unroll
                for (int mt = 0; mt < 2; mt++)
#pragma unroll
                    for (int nt = 0; nt < 8; nt++) {
                        int n = n0w + nt * 8 + np;
                        float b0 = __ldg(bias + vcol0 + n), b1 = __ldg(bias + vcol0 + n + 1);
                        int m = m0w + mt * 16 + gm;
                        stage[(size_t)n * 136 + m]           = __float2half(acc[mt][nt][0] + b0);
                        stage[(size_t)(n + 1) * 136 + m]     = __float2half(acc[mt][nt][1] + b1);
                        stage[(size_t)n * 136 + m + 8]       = __float2half(acc[mt][nt][2] + b0);
                        stage[(size_t)(n + 1) * 136 + m + 8] = __float2half(acc[mt][nt][3] + b1);
                    }
                __syncthreads();
                const int z = row0 >> 11, tok0 = row0 & (TT - 1);
                const int r = threadIdx.x >> 1, part = (threadIdx.x & 1) * 8;
                const uint4* srcrow = (const uint4*)(stage + (size_t)r * 136);
                __half* dst = g_vt + ((size_t)z * CC + vcol0 + r) * TT + tok0;
#pragma unroll
                for (int i = 0; i < 8; i++)
                    ((uint4*)dst)[part + i] = srcrow[part + i];
                RELEASE(&g_done_v[z * 8 + (vcol0 >> 7)]);
            }
        } else if (t < OFF_SM) {
            // ---- scores tile, by descending (diagonal row-blocks first) ----
            const unsigned int ts = t - OFF_SCO;
            const int z = (int)(ts & 3);
            const int idx = 135 - (int)(ts >> 2);
            int by = (int)((sqrtf(8.0f * idx + 1.0f) - 1.0f) * 0.5f);
            while ((by + 1) * (by + 2) / 2 <= idx) by++;
            while (by * (by + 1) / 2 > idx) by--;
            const int bx = idx - by * (by + 1) / 2;
            const int t0 = by * 128, s0 = bx * 128;

            ACQUIRE(&g_done_q[z * 16 + by], 8);
            ACQUIRE(&g_done_k[z * 16 + bx], 8);

            ACC_INIT();
            const __half* Ag = g_qh + ((size_t)z * TT + t0) * CC;
            const __half* Bg = g_kh + ((size_t)z * TT + s0) * CC;
            gemm_mainloop(sm, Ag, CC, Bg, CC, CC / 64, acc);

            EPI_COORDS();
            float* S = g_s + ((size_t)z * TT + t0) * TT + s0;
#pragma unroll
            for (int mt = 0; mt < 2; mt++)
#pragma unroll
                for (int nt = 0; nt < 8; nt++) {
                    int m = m0w + mt * 16 + gm, n = n0w + nt * 8 + np;
                    *(float2*)(S + (size_t)m * TT + n)       = make_float2(acc[mt][nt][0], acc[mt][nt][1]);
                    *(float2*)(S + (size_t)(m + 8) * TT + n) = make_float2(acc[mt][nt][2], acc[mt][nt][3]);
                }
            RELEASE(&g_done_sco[z * 16 + by]);
        } else if (t < OFF_PV) {
            // ---- softmax group: 8 rows, smem staging ----
            const int j = (int)(t - OFF_SM);
            const int by = 15 - (j >> 6);
            const int z  = (j >> 4) & 3;
            const int grp = j & 15;
            ACQUIRE(&g_done_sco[z * 16 + by], by + 1);

            float* shall = (float*)dynsm;        // 8 rows x 2048 floats = 64KB
            const int warp = threadIdx.x >> 5, lane = threadIdx.x & 31;
            const int trow = by * 128 + grp * 8 + warp;
            const size_t off = ((size_t)z * TT + trow) * TT;
            const float4* __restrict__ S4 = (const float4*)(g_s + off);
            float* sh = shall + warp * TT;
            const int n = trow + 1;
            const int nch = (n + 3) >> 2;

            float mx = -INFINITY;
            for (int c = lane; c < nch; c += 32) {
                float4 v = S4[c];
                int base = c * 4;
                if (base + 3 >= n) {
                    if (base + 1 >= n) v.y = -INFINITY;
                    if (base + 2 >= n) v.z = -INFINITY;
                    if (base + 3 >= n) v.w = -INFINITY;
                }
                ((float4*)sh)[c] = v;
                mx = fmaxf(mx, fmaxf(fmaxf(v.x, v.y), fmaxf(v.z, v.w)));
            }
#pragma unroll
            for (int o = 16; o > 0; o >>= 1)
                mx = fmaxf(mx, __shfl_xor_sync(0xFFFFFFFFu, mx, o));

            float sum = 0.f;
            for (int c = lane; c < nch; c += 32) {
                float4 v = ((float4*)sh)[c];
                v.x = __expf(v.x - mx); v.y = __expf(v.y - mx);
                v.z = __expf(v.z - mx); v.w = __expf(v.w - mx);
                ((float4*)sh)[c] = v;
                sum += v.x + v.y + v.z + v.w;
            }
#pragma unroll
            for (int o = 16; o > 0; o >>= 1)
                sum += __shfl_xor_sync(0xFFFFFFFFu, sum, o);
            const float inv = 1.f / sum;
            __syncwarp();

            const int zEnd = ((trow >> 7) + 1) << 7;
            __half* P = g_ph + off;
            for (int c = lane; c < (zEnd >> 3); c += 32) {
                int i0 = c * 8;
                __half h[8];
#pragma unroll
                for (int jj = 0; jj < 8; jj++) {
                    int idx2 = i0 + jj;
                    h[jj] = __float2half((idx2 < n) ? sh[idx2] * inv : 0.f);
                }
                *(uint4*)(P + i0) = *(uint4*)h;
            }
            RELEASE(&g_done_sm[z * 16 + by]);
        } else {
            // ---- PV tile (heavy-first) ----
            const int p = (int)(t - OFF_PV);
            const int by = 15 - (p >> 5);
            const int z  = (p >> 3) & 3;
            const int bx = p & 7;
            ACQUIRE(&g_done_sm[z * 16 + by], 16);
            ACQUIRE(&g_done_v[z * 8 + bx], 16);

            const int t0 = by * 128, c0 = bx * 128;
            ACC_INIT();
            const __half* Ag = g_ph + ((size_t)z * TT + t0) * TT;
            const __half* Bg = g_vt + ((size_t)z * CC + c0) * TT;
            gemm_mainloop(sm, Ag, TT, Bg, TT, (by + 1) * 2, acc);

            EPI_COORDS();
            float* O = Out + ((size_t)z * TT + t0) * CC + c0;
#pragma unroll
            for (int mt = 0; mt < 2; mt++)
#pragma unroll
                for (int nt = 0; nt < 8; nt++) {
                    int m = m0w + mt * 16 + gm, n = n0w + nt * 8 + np;
                    *(float2*)(O + (size_t)m * CC + n)       = make_float2(acc[mt][nt][0], acc[mt][nt][1]);
                    *(float2*)(O + (size_t)(m + 8) * CC + n) = make_float2(acc[mt][nt][2], acc[mt][nt][3]);
                }
        }
        __syncthreads();   // quiesce smem / s_tile before next steal
    }
}

// ------------------------- launch --------------------------------------------
extern "C" void kernel_launch(void* const* d_in, const int* in_sizes, int n_in,
                              void* d_out, int out_size) {
    const float* x  = (const float*)d_in[0];
    const float* Wq = (const float*)d_in[1];
    const float* bq = (const float*)d_in[2];
    const float* Wk = (const float*)d_in[3];
    const float* bk = (const float*)d_in[4];
    const float* Wv = (const float*)d_in[5];
    const float* bv = (const float*)d_in[6];
    float* out = (float*)d_out;

    cudaFuncSetAttribute(mega_kernel, cudaFuncAttributeMaxDynamicSharedMemorySize, DYN_B);

    convert_all_kernel<<<8192 + 3072, 256>>>(x, Wq, Wk, Wv);
    mega_kernel<<<NPERS, NTH, DYN_B>>>(bq, bk, bv, out);
}